// round 12
// baseline (speedup 1.0000x reference)
#include <cuda_runtime.h>
#include <cuda_bf16.h>
#include <cstdint>
#include <math.h>

#define BB 2
#define CC 128
#define WW 96
#define HWD 9216
#define TQ 128
#define TK 128
#define NKT (HWD/TK)          // 72
#define SP 136                // padded smem row stride in bf16
#define SPB (SP*2)            // 272 bytes (16B-aligned, bank-rotating)
#define TILEB (128*SPB)       // 34816 B per 128x128 bf16 tile
#define STAGEB (2*TILEB)      // hi+lo per k stage

// Decomposed, normalized features: [B][HW][C] bf16, row-major.
__device__ __nv_bfloat16 g_qhi[BB*HWD*CC];
__device__ __nv_bfloat16 g_qlo[BB*HWD*CC];
__device__ __nv_bfloat16 g_khi[BB*HWD*CC];
__device__ __nv_bfloat16 g_klo[BB*HWD*CC];

// ---------------------------------------------------------------------------
// exp(s*a) for a in [-1.02, 1.02], s = 1/(sqrt(128)*0.1) = 0.883883476...
// Degree-9 Taylor with the scale folded into the coefficients; pure FMA pipe
// (no MUFU). Max rel err < 3e-7 on the domain. Valid because features are
// unit vectors => |dot| <= 1, so the reference's +-50 clamp never binds.
// ---------------------------------------------------------------------------
__device__ __forceinline__ float exp_scaled(float a) {
    const float c9 = 9.073900e-7f;      // s^9/9!
    const float c8 = 9.239313e-6f;      // s^8/8!
    const float c7 = 8.362471e-5f;      // s^7/7!
    const float c6 = 6.622738e-4f;      // s^6/6!
    const float c5 = 4.495664e-3f;      // s^5/5!
    const float c4 = 2.543132e-2f;      // s^4/4!
    const float c3 = 1.150890e-1f;      // s^3/3!
    const float c2 = 3.90625e-1f;       // s^2/2  (s^2 = 0.78125 exact)
    const float c1 = 0.8838834764831844f;
    float p = c9;
    p = fmaf(p, a, c8); p = fmaf(p, a, c7); p = fmaf(p, a, c6);
    p = fmaf(p, a, c5); p = fmaf(p, a, c4); p = fmaf(p, a, c3);
    p = fmaf(p, a, c2); p = fmaf(p, a, c1); p = fmaf(p, a, 1.0f);
    return p;
}

// ---------------------------------------------------------------------------
// PTX helpers (all non-'a' baseline PTX: mbarrier, cp.async.bulk, mma.sync)
// ---------------------------------------------------------------------------
__device__ __forceinline__ uint32_t smem_u32(const void* p) {
    uint32_t a;
    asm("{ .reg .u64 t; cvta.to.shared.u64 t, %1; cvt.u32.u64 %0, t; }" : "=r"(a) : "l"(p));
    return a;
}
__device__ __forceinline__ void mbar_init(uint32_t a, uint32_t n) {
    asm volatile("mbarrier.init.shared.b64 [%0], %1;" :: "r"(a), "r"(n) : "memory");
}
__device__ __forceinline__ void mbar_expect_tx(uint32_t a, uint32_t bytes) {
    asm volatile("mbarrier.arrive.expect_tx.shared.b64 _, [%0], %1;"
                 :: "r"(a), "r"(bytes) : "memory");
}
__device__ __forceinline__ void mbar_wait(uint32_t addr, uint32_t parity) {
    uint32_t done;
    asm volatile(
        "{\n\t.reg .pred p;\n\t"
        "mbarrier.try_wait.parity.acquire.cta.shared::cta.b64 p, [%1], %2;\n\t"
        "selp.b32 %0, 1, 0, p;\n\t}"
        : "=r"(done) : "r"(addr), "r"(parity) : "memory");
    if (!done) {
        asm volatile(
            "{\n\t.reg .pred P1;\n\t"
            "WAIT_LOOP_%=:\n\t"
            "mbarrier.try_wait.parity.acquire.cta.shared::cta.b64 P1, [%0], %1, 0x989680;\n\t"
            "@P1 bra.uni WAIT_DONE_%=;\n\t"
            "bra.uni WAIT_LOOP_%=;\n\t"
            "WAIT_DONE_%=:\n\t}"
            :: "r"(addr), "r"(parity) : "memory");
    }
}
__device__ __forceinline__ void bulk_copy(uint32_t dst, const void* src, uint32_t mbar) {
    asm volatile(
        "cp.async.bulk.shared::cta.global.mbarrier::complete_tx::bytes [%0], [%1], %2, [%3];"
        :: "r"(dst), "l"(src), "n"(256), "r"(mbar) : "memory");
}

// mma.sync m16n8k16 row.col bf16 -> fp32 (baseline sm_80+ PTX)
#define MMA16816(d, a, b) \
    asm volatile("mma.sync.aligned.m16n8k16.row.col.f32.bf16.bf16.f32 " \
        "{%0,%1,%2,%3}, {%4,%5,%6,%7}, {%8,%9}, {%0,%1,%2,%3};" \
        : "+f"((d)[0]), "+f"((d)[1]), "+f"((d)[2]), "+f"((d)[3]) \
        : "r"((a)[0]), "r"((a)[1]), "r"((a)[2]), "r"((a)[3]), \
          "r"((b)[0]), "r"((b)[1]))

// ---------------------------------------------------------------------------
// Kernel 1: normalize + transpose + split-bf16 decompose.
// grid: (HWD/128, BB, 2{L,R})
// ---------------------------------------------------------------------------
__global__ void __launch_bounds__(256)
decomp_kernel(const float* __restrict__ fL, const float* __restrict__ fR) {
    __shared__ float s[CC*129];
    __shared__ float s_part[256];
    __shared__ float s_inv[128];

    const int pbase = blockIdx.x * 128;
    const int b     = blockIdx.y;
    const float* src = (blockIdx.z ? fR : fL) + (size_t)b * CC * HWD;
    __nv_bfloat16* dhi = blockIdx.z ? g_khi : g_qhi;
    __nv_bfloat16* dlo = blockIdx.z ? g_klo : g_qlo;
    const int tid = threadIdx.x;

    for (int idx = tid; idx < CC*32; idx += 256) {
        int c  = idx >> 5;
        int p4 = (idx & 31) << 2;
        float4 v = *reinterpret_cast<const float4*>(src + (size_t)c*HWD + pbase + p4);
        float* d = s + c*129 + p4;
        d[0]=v.x; d[1]=v.y; d[2]=v.z; d[3]=v.w;
    }
    __syncthreads();
    {
        int pos = tid & 127, half = tid >> 7;
        float ss = 0.f;
#pragma unroll 8
        for (int c = half*64; c < half*64 + 64; ++c) { float v = s[c*129 + pos]; ss += v*v; }
        s_part[tid] = ss;
    }
    __syncthreads();
    if (tid < 128)
        s_inv[tid] = 1.0f / fmaxf(sqrtf(s_part[tid] + s_part[tid+128]), 1e-6f);
    __syncthreads();

    for (int idx = tid; idx < 128*64; idx += 256) {
        int c2 = idx & 63, pos = idx >> 6;
        float inv = s_inv[pos];
        float f0 = s[(2*c2  )*129 + pos] * inv;
        float f1 = s[(2*c2+1)*129 + pos] * inv;
        __nv_bfloat162 h = __floats2bfloat162_rn(f0, f1);
        float l0 = f0 - __bfloat162float(h.x);
        float l1 = f1 - __bfloat162float(h.y);
        __nv_bfloat162 l = __floats2bfloat162_rn(l0, l1);
        size_t o = ((size_t)b*HWD + pbase + pos) * CC + 2*c2;
        *reinterpret_cast<uint32_t*>(&dhi[o]) = *reinterpret_cast<const uint32_t*>(&h);
        *reinterpret_cast<uint32_t*>(&dlo[o]) = *reinterpret_cast<const uint32_t*>(&l);
    }
}

// ---------------------------------------------------------------------------
// Kernel 2: mma.sync correlation + in-register one-pass softmax (FMA-pipe exp).
// CTA: 128q x 128k tile per kt; 8 warps as 2(m) x 4(n), warp tile 64x32.
// smem: Qhi | Qlo | Kstage0{hi,lo} | Kstage1{hi,lo} | mbarriers
// ---------------------------------------------------------------------------
extern __shared__ char dsm[];

__global__ void __launch_bounds__(256, 1)
corr_kernel(float* __restrict__ out) {
    const int tid  = threadIdx.x;
    const int wid  = tid >> 5;
    const int lane = tid & 31;
    const int g    = lane >> 2;       // fragment group row
    const int tig  = lane & 3;        // fragment thread-in-group
    const int wm   = wid >> 2;        // warp m index (0..1)
    const int wn   = wid & 3;         // warp n index (0..3)
    const int b     = blockIdx.y;
    const int qbase = blockIdx.x * TQ;

    char* sQhi = dsm;
    char* sQlo = dsm + TILEB;
    char* sK   = dsm + 2*TILEB;
    const uint32_t mbar0 = smem_u32(dsm) + (uint32_t)(2*TILEB + 2*STAGEB);
    const uint32_t sK0   = smem_u32(sK);

    const __nv_bfloat16* qhi  = g_qhi + ((size_t)b*HWD + qbase) * CC;
    const __nv_bfloat16* qlo  = g_qlo + ((size_t)b*HWD + qbase) * CC;
    const __nv_bfloat16* khiB = g_khi + (size_t)b*HWD*CC;
    const __nv_bfloat16* kloB = g_klo + (size_t)b*HWD*CC;

    if (tid == 0) { mbar_init(mbar0, 1); mbar_init(mbar0 + 8, 1); }

    // ---- load Q tiles into padded smem ----
    for (int idx = tid; idx < 128*16; idx += 256) {
        int row = idx >> 4, c4 = idx & 15;
        *reinterpret_cast<float4*>(sQhi + row*SPB + c4*16) =
            reinterpret_cast<const float4*>(qhi + (size_t)row*CC)[c4];
        *reinterpret_cast<float4*>(sQlo + row*SPB + c4*16) =
            reinterpret_cast<const float4*>(qlo + (size_t)row*CC)[c4];
    }
    __syncthreads();   // mbarriers + Q visible

    // ---- stage issue: warp 0, 256 bulk copies of 256B (hi+lo rows) ----
    auto issue_stage = [&](int kt) {
        if (tid < 32) {
            const int buf = kt & 1;
            const uint32_t mb = mbar0 + buf*8;
            if (tid == 0) mbar_expect_tx(mb, 2*128*256);
            __syncwarp();
            const uint32_t dhi = sK0 + buf*STAGEB;
            const __nv_bfloat16* shi = khiB + (size_t)kt*TK*CC;
            const __nv_bfloat16* slo = kloB + (size_t)kt*TK*CC;
            for (int r = tid; r < 128; r += 32) {
                bulk_copy(dhi + r*SPB,         shi + (size_t)r*CC, mb);
                bulk_copy(dhi + TILEB + r*SPB, slo + (size_t)r*CC, mb);
            }
        }
    };

    issue_stage(0);
    issue_stage(1);
    uint32_t ph0 = 0, ph1 = 0;

    // per-lane softmax accumulators: 8 row slots (4 m-blocks x {g, g+8}).
    // pM tracked in dot space (monotone under positive scale).
    float pS[8], pX[8], pY[8], pM[8];
#pragma unroll
    for (int i = 0; i < 8; ++i) { pS[i]=0.f; pX[i]=0.f; pY[i]=0.f; pM[i]=-4.f; }

    // fragment base byte offsets within a tile
    const int aoff = (wm*64 + g)*SPB + tig*4;
    const int boff = (wn*32 + g)*SPB + tig*4;

    for (int kt = 0; kt < NKT; ++kt) {
        const int buf = kt & 1;
        if (buf == 0) { mbar_wait(mbar0,     ph0); ph0 ^= 1; }
        else          { mbar_wait(mbar0 + 8, ph1); ph1 ^= 1; }

        const char* Bhi = sK + buf*STAGEB;
        const char* Blo = Bhi + TILEB;

        float acc[4][4][4];
#pragma unroll
        for (int mb = 0; mb < 4; ++mb)
#pragma unroll
            for (int nb = 0; nb < 4; ++nb)
#pragma unroll
                for (int r = 0; r < 4; ++r) acc[mb][nb][r] = 0.f;

#pragma unroll
        for (int ks = 0; ks < 8; ++ks) {
            const int co = ks*32;   // 16 chans * 2B
            uint32_t a[4][4], bh[4][2], bl[4][2];
            // A = Q-hi fragments
#pragma unroll
            for (int mb = 0; mb < 4; ++mb) {
                const char* p = sQhi + aoff + mb*16*SPB + co;
                a[mb][0] = *reinterpret_cast<const uint32_t*>(p);
                a[mb][1] = *reinterpret_cast<const uint32_t*>(p + 8*SPB);
                a[mb][2] = *reinterpret_cast<const uint32_t*>(p + 16);
                a[mb][3] = *reinterpret_cast<const uint32_t*>(p + 8*SPB + 16);
            }
#pragma unroll
            for (int nb = 0; nb < 4; ++nb) {
                const char* p = Bhi + boff + nb*8*SPB + co;
                bh[nb][0] = *reinterpret_cast<const uint32_t*>(p);
                bh[nb][1] = *reinterpret_cast<const uint32_t*>(p + 16);
            }
            // hi * hi
#pragma unroll
            for (int mb = 0; mb < 4; ++mb)
#pragma unroll
                for (int nb = 0; nb < 4; ++nb)
                    MMA16816(acc[mb][nb], a[mb], bh[nb]);
            // hi * lo
#pragma unroll
            for (int nb = 0; nb < 4; ++nb) {
                const char* p = Blo + boff + nb*8*SPB + co;
                bl[nb][0] = *reinterpret_cast<const uint32_t*>(p);
                bl[nb][1] = *reinterpret_cast<const uint32_t*>(p + 16);
            }
#pragma unroll
            for (int mb = 0; mb < 4; ++mb)
#pragma unroll
                for (int nb = 0; nb < 4; ++nb)
                    MMA16816(acc[mb][nb], a[mb], bl[nb]);
            // lo * hi (reuse a[] for Q-lo)
#pragma unroll
            for (int mb = 0; mb < 4; ++mb) {
                const char* p = sQlo + aoff + mb*16*SPB + co;
                a[mb][0] = *reinterpret_cast<const uint32_t*>(p);
                a[mb][1] = *reinterpret_cast<const uint32_t*>(p + 8*SPB);
                a[mb][2] = *reinterpret_cast<const uint32_t*>(p + 16);
                a[mb][3] = *reinterpret_cast<const uint32_t*>(p + 8*SPB + 16);
            }
#pragma unroll
            for (int mb = 0; mb < 4; ++mb)
#pragma unroll
                for (int nb = 0; nb < 4; ++nb)
                    MMA16816(acc[mb][nb], a[mb], bh[nb]);
        }

        __syncthreads();                    // all warps done reading sK[buf]
        if (kt + 2 < NKT) issue_stage(kt + 2);

        // ---- fold 64x32 logits into per-lane running softmax (FMA pipe only) ----
#pragma unroll
        for (int nb = 0; nb < 4; ++nb) {
            const int col = kt*TK + wn*32 + nb*8 + tig*2;   // even; cx+1 never wraps
            const int cyi = col / WW;
            const float cy = (float)cyi;
            const float cx0 = (float)(col - cyi*WW);
#pragma unroll
            for (int mb = 0; mb < 4; ++mb) {
#pragma unroll
                for (int r = 0; r < 4; ++r) {
                    const int slot = mb*2 + (r >> 1);       // r0,r1 -> row g; r2,r3 -> g+8
                    const float cx = (r & 1) ? (cx0 + 1.f) : cx0;
                    float d = acc[mb][nb][r];
                    d = fminf(fmaxf(d, -1.02f), 1.02f);     // |dot|<=1; ref's +-50 clamp is a no-op
                    float e = exp_scaled(d);
                    pS[slot] += e;
                    pX[slot] += e * cx;
                    pY[slot] += e * cy;
                    pM[slot]  = fmaxf(pM[slot], d);
                }
            }
        }
    }

    // ---- reduce across tig lanes (same row, different cols) ----
#pragma unroll
    for (int s = 0; s < 8; ++s) {
#pragma unroll
        for (int d = 1; d <= 2; d <<= 1) {
            pS[s] += __shfl_xor_sync(0xffffffff, pS[s], d);
            pX[s] += __shfl_xor_sync(0xffffffff, pX[s], d);
            pY[s] += __shfl_xor_sync(0xffffffff, pY[s], d);
            pM[s]  = fmaxf(pM[s], __shfl_xor_sync(0xffffffff, pM[s], d));
        }
    }

    // ---- cross-warp (wn) reduction via smem; reuse sQhi region ----
    float* red = reinterpret_cast<float*>(dsm);   // [4 stats][128 rows][4 wn]
    if (tig == 0) {
#pragma unroll
        for (int s = 0; s < 8; ++s) {
            int row = wm*64 + (s >> 1)*16 + g + (s & 1)*8;
            red[(0*128 + row)*4 + wn] = pS[s];
            red[(1*128 + row)*4 + wn] = pX[s];
            red[(2*128 + row)*4 + wn] = pY[s];
            red[(3*128 + row)*4 + wn] = pM[s];
        }
    }
    __syncthreads();

    if (tid < 128) {
        const int row = tid;
        float s = 0.f, xs = 0.f, ys = 0.f, m = -4.f;
#pragma unroll
        for (int t = 0; t < 4; ++t) {
            s  += red[(0*128 + row)*4 + t];
            xs += red[(1*128 + row)*4 + t];
            ys += red[(2*128 + row)*4 + t];
            m   = fmaxf(m, red[(3*128 + row)*4 + t]);
        }
        const int p = qbase + row;
        const float xsrc = (float)(p % WW);
        const float ysrc = (float)(p / WW);
        const float invs = 1.0f / s;
        out[((size_t)b*2 + 0)*HWD + p] = xs * invs - xsrc;
        out[((size_t)b*2 + 1)*HWD + p] = ys * invs - ysrc;
        out[(size_t)BB*2*HWD + (size_t)b*HWD + p] = exp_scaled(m) * invs;
    }
}

// ---------------------------------------------------------------------------
extern "C" void kernel_launch(void* const* d_in, const int* in_sizes, int n_in,
                              void* d_out, int out_size) {
    const float* fL = (const float*)d_in[0];
    const float* fR = (const float*)d_in[1];
    float* out = (float*)d_out;

    {
        dim3 grid(HWD/128, BB, 2);
        decomp_kernel<<<grid, 256>>>(fL, fR);
    }
    {
        const int smem_bytes = 2*TILEB + 2*STAGEB + 32;   // 208928
        cudaFuncSetAttribute(corr_kernel,
                             cudaFuncAttributeMaxDynamicSharedMemorySize, smem_bytes);
        dim3 grid(HWD / TQ, BB);
        corr_kernel<<<grid, 256, smem_bytes>>>(out);
    }
}

// round 13
// speedup vs baseline: 1.0536x; 1.0536x over previous
#include <cuda_runtime.h>
#include <cuda_bf16.h>
#include <cstdint>
#include <math.h>

#define BB 2
#define CC 128
#define WW 96
#define HWD 9216
#define TQ 128
#define TK 128
#define NKT (HWD/TK)          // 72
#define NTHREADS 512
#define SP 136                // padded smem row stride in bf16
#define SPB (SP*2)            // 272 bytes (16B-aligned, bank-rotating)
#define TILEB (128*SPB)       // 34816 B per 128x128 bf16 tile
#define STAGEB (2*TILEB)      // hi+lo per k stage

// Decomposed, normalized features: [B][HW][C] bf16, row-major.
__device__ __nv_bfloat16 g_qhi[BB*HWD*CC];
__device__ __nv_bfloat16 g_qlo[BB*HWD*CC];
__device__ __nv_bfloat16 g_khi[BB*HWD*CC];
__device__ __nv_bfloat16 g_klo[BB*HWD*CC];

// ---------------------------------------------------------------------------
// exp(s*a) for a in [-1.02, 1.02], s = 1/(sqrt(128)*0.1). Degree-9 Taylor with
// the scale folded in; pure FMA pipe. Max rel err < 3e-7 on the domain.
// Valid because features are unit vectors => |dot| <= 1 (ref's +-50 clamp
// never binds).
// ---------------------------------------------------------------------------
__device__ __forceinline__ float exp_scaled(float a) {
    const float c9 = 9.073900e-7f;
    const float c8 = 9.239313e-6f;
    const float c7 = 8.362471e-5f;
    const float c6 = 6.622738e-4f;
    const float c5 = 4.495664e-3f;
    const float c4 = 2.543132e-2f;
    const float c3 = 1.150890e-1f;
    const float c2 = 3.90625e-1f;       // s^2/2 (s^2 = 0.78125 exact)
    const float c1 = 0.8838834764831844f;
    float p = c9;
    p = fmaf(p, a, c8); p = fmaf(p, a, c7); p = fmaf(p, a, c6);
    p = fmaf(p, a, c5); p = fmaf(p, a, c4); p = fmaf(p, a, c3);
    p = fmaf(p, a, c2); p = fmaf(p, a, c1); p = fmaf(p, a, 1.0f);
    return p;
}

// ---------------------------------------------------------------------------
// PTX helpers (all non-'a' baseline PTX: mbarrier, cp.async.bulk, mma.sync)
// ---------------------------------------------------------------------------
__device__ __forceinline__ uint32_t smem_u32(const void* p) {
    uint32_t a;
    asm("{ .reg .u64 t; cvta.to.shared.u64 t, %1; cvt.u32.u64 %0, t; }" : "=r"(a) : "l"(p));
    return a;
}
__device__ __forceinline__ void mbar_init(uint32_t a, uint32_t n) {
    asm volatile("mbarrier.init.shared.b64 [%0], %1;" :: "r"(a), "r"(n) : "memory");
}
__device__ __forceinline__ void mbar_expect_tx(uint32_t a, uint32_t bytes) {
    asm volatile("mbarrier.arrive.expect_tx.shared.b64 _, [%0], %1;"
                 :: "r"(a), "r"(bytes) : "memory");
}
__device__ __forceinline__ void mbar_wait(uint32_t addr, uint32_t parity) {
    uint32_t done;
    asm volatile(
        "{\n\t.reg .pred p;\n\t"
        "mbarrier.try_wait.parity.acquire.cta.shared::cta.b64 p, [%1], %2;\n\t"
        "selp.b32 %0, 1, 0, p;\n\t}"
        : "=r"(done) : "r"(addr), "r"(parity) : "memory");
    if (!done) {
        asm volatile(
            "{\n\t.reg .pred P1;\n\t"
            "WAIT_LOOP_%=:\n\t"
            "mbarrier.try_wait.parity.acquire.cta.shared::cta.b64 P1, [%0], %1, 0x989680;\n\t"
            "@P1 bra.uni WAIT_DONE_%=;\n\t"
            "bra.uni WAIT_LOOP_%=;\n\t"
            "WAIT_DONE_%=:\n\t}"
            :: "r"(addr), "r"(parity) : "memory");
    }
}
__device__ __forceinline__ void bulk_copy(uint32_t dst, const void* src, uint32_t mbar) {
    asm volatile(
        "cp.async.bulk.shared::cta.global.mbarrier::complete_tx::bytes [%0], [%1], %2, [%3];"
        :: "r"(dst), "l"(src), "n"(256), "r"(mbar) : "memory");
}

// mma.sync m16n8k16 row.col bf16 -> fp32 (baseline sm_80+ PTX)
#define MMA16816(d, a, b) \
    asm volatile("mma.sync.aligned.m16n8k16.row.col.f32.bf16.bf16.f32 " \
        "{%0,%1,%2,%3}, {%4,%5,%6,%7}, {%8,%9}, {%0,%1,%2,%3};" \
        : "+f"((d)[0]), "+f"((d)[1]), "+f"((d)[2]), "+f"((d)[3]) \
        : "r"((a)[0]), "r"((a)[1]), "r"((a)[2]), "r"((a)[3]), \
          "r"((b)[0]), "r"((b)[1]))

// ---------------------------------------------------------------------------
// Kernel 1: normalize + transpose + split-bf16 decompose.
// grid: (HWD/128, BB, 2{L,R})
// ---------------------------------------------------------------------------
__global__ void __launch_bounds__(256)
decomp_kernel(const float* __restrict__ fL, const float* __restrict__ fR) {
    __shared__ float s[CC*129];
    __shared__ float s_part[256];
    __shared__ float s_inv[128];

    const int pbase = blockIdx.x * 128;
    const int b     = blockIdx.y;
    const float* src = (blockIdx.z ? fR : fL) + (size_t)b * CC * HWD;
    __nv_bfloat16* dhi = blockIdx.z ? g_khi : g_qhi;
    __nv_bfloat16* dlo = blockIdx.z ? g_klo : g_qlo;
    const int tid = threadIdx.x;

    for (int idx = tid; idx < CC*32; idx += 256) {
        int c  = idx >> 5;
        int p4 = (idx & 31) << 2;
        float4 v = *reinterpret_cast<const float4*>(src + (size_t)c*HWD + pbase + p4);
        float* d = s + c*129 + p4;
        d[0]=v.x; d[1]=v.y; d[2]=v.z; d[3]=v.w;
    }
    __syncthreads();
    {
        int pos = tid & 127, half = tid >> 7;
        float ss = 0.f;
#pragma unroll 8
        for (int c = half*64; c < half*64 + 64; ++c) { float v = s[c*129 + pos]; ss += v*v; }
        s_part[tid] = ss;
    }
    __syncthreads();
    if (tid < 128)
        s_inv[tid] = 1.0f / fmaxf(sqrtf(s_part[tid] + s_part[tid+128]), 1e-6f);
    __syncthreads();

    for (int idx = tid; idx < 128*64; idx += 256) {
        int c2 = idx & 63, pos = idx >> 6;
        float inv = s_inv[pos];
        float f0 = s[(2*c2  )*129 + pos] * inv;
        float f1 = s[(2*c2+1)*129 + pos] * inv;
        __nv_bfloat162 h = __floats2bfloat162_rn(f0, f1);
        float l0 = f0 - __bfloat162float(h.x);
        float l1 = f1 - __bfloat162float(h.y);
        __nv_bfloat162 l = __floats2bfloat162_rn(l0, l1);
        size_t o = ((size_t)b*HWD + pbase + pos) * CC + 2*c2;
        *reinterpret_cast<uint32_t*>(&dhi[o]) = *reinterpret_cast<const uint32_t*>(&h);
        *reinterpret_cast<uint32_t*>(&dlo[o]) = *reinterpret_cast<const uint32_t*>(&l);
    }
}

// ---------------------------------------------------------------------------
// Kernel 2: mma.sync correlation + in-register one-pass softmax.
// CTA: 128q x 128k tile per kt; 16 warps as 4(m) x 4(n), warp tile 32x32.
// 4 warps/SMSP hide LDS/HMMA/poly latency; tensor pipe becomes the limiter.
// smem: Qhi | Qlo | Kstage0{hi,lo} | Kstage1{hi,lo} | mbarriers
// ---------------------------------------------------------------------------
extern __shared__ char dsm[];

__global__ void __launch_bounds__(NTHREADS, 1)
corr_kernel(float* __restrict__ out) {
    const int tid  = threadIdx.x;
    const int wid  = tid >> 5;
    const int lane = tid & 31;
    const int g    = lane >> 2;       // fragment group row
    const int tig  = lane & 3;        // fragment thread-in-group
    const int wm   = wid >> 2;        // warp m index (0..3)
    const int wn   = wid & 3;         // warp n index (0..3)
    const int b     = blockIdx.y;
    const int qbase = blockIdx.x * TQ;

    char* sQhi = dsm;
    char* sQlo = dsm + TILEB;
    char* sK   = dsm + 2*TILEB;
    const uint32_t mbar0 = smem_u32(dsm) + (uint32_t)(2*TILEB + 2*STAGEB);
    const uint32_t sK0   = smem_u32(sK);

    const __nv_bfloat16* qhi  = g_qhi + ((size_t)b*HWD + qbase) * CC;
    const __nv_bfloat16* qlo  = g_qlo + ((size_t)b*HWD + qbase) * CC;
    const __nv_bfloat16* khiB = g_khi + (size_t)b*HWD*CC;
    const __nv_bfloat16* kloB = g_klo + (size_t)b*HWD*CC;

    if (tid == 0) { mbar_init(mbar0, 1); mbar_init(mbar0 + 8, 1); }

    // ---- load Q tiles into padded smem ----
    for (int idx = tid; idx < 128*16; idx += NTHREADS) {
        int row = idx >> 4, c4 = idx & 15;
        *reinterpret_cast<float4*>(sQhi + row*SPB + c4*16) =
            reinterpret_cast<const float4*>(qhi + (size_t)row*CC)[c4];
        *reinterpret_cast<float4*>(sQlo + row*SPB + c4*16) =
            reinterpret_cast<const float4*>(qlo + (size_t)row*CC)[c4];
    }
    __syncthreads();   // mbarriers + Q visible

    // ---- stage issue: warp 0, 256 bulk copies of 256B (hi+lo rows) ----
    auto issue_stage = [&](int kt) {
        if (tid < 32) {
            const int buf = kt & 1;
            const uint32_t mb = mbar0 + buf*8;
            if (tid == 0) mbar_expect_tx(mb, 2*128*256);
            __syncwarp();
            const uint32_t dhi = sK0 + buf*STAGEB;
            const __nv_bfloat16* shi = khiB + (size_t)kt*TK*CC;
            const __nv_bfloat16* slo = kloB + (size_t)kt*TK*CC;
            for (int r = tid; r < 128; r += 32) {
                bulk_copy(dhi + r*SPB,         shi + (size_t)r*CC, mb);
                bulk_copy(dhi + TILEB + r*SPB, slo + (size_t)r*CC, mb);
            }
        }
    };

    issue_stage(0);
    issue_stage(1);
    uint32_t ph0 = 0, ph1 = 0;

    // per-lane softmax accumulators: 4 row slots (2 m-blocks x {g, g+8}).
    // pM tracked in dot space (monotone under positive scale).
    float pS[4], pX[4], pY[4], pM[4];
#pragma unroll
    for (int i = 0; i < 4; ++i) { pS[i]=0.f; pX[i]=0.f; pY[i]=0.f; pM[i]=-4.f; }

    // fragment base byte offsets within a tile
    const int aoff = (wm*32 + g)*SPB + tig*4;
    const int boff = (wn*32 + g)*SPB + tig*4;

    for (int kt = 0; kt < NKT; ++kt) {
        const int buf = kt & 1;
        if (buf == 0) { mbar_wait(mbar0,     ph0); ph0 ^= 1; }
        else          { mbar_wait(mbar0 + 8, ph1); ph1 ^= 1; }

        const char* Bhi = sK + buf*STAGEB;
        const char* Blo = Bhi + TILEB;

        float acc[2][4][4];
#pragma unroll
        for (int mb = 0; mb < 2; ++mb)
#pragma unroll
            for (int nb = 0; nb < 4; ++nb)
#pragma unroll
                for (int r = 0; r < 4; ++r) acc[mb][nb][r] = 0.f;

#pragma unroll
        for (int ks = 0; ks < 8; ++ks) {
            const int co = ks*32;   // 16 chans * 2B
            uint32_t a[2][4], bh[4][2], bl[4][2];
            // A = Q-hi fragments (2 m-blocks of 16 rows)
#pragma unroll
            for (int mb = 0; mb < 2; ++mb) {
                const char* p = sQhi + aoff + mb*16*SPB + co;
                a[mb][0] = *reinterpret_cast<const uint32_t*>(p);
                a[mb][1] = *reinterpret_cast<const uint32_t*>(p + 8*SPB);
                a[mb][2] = *reinterpret_cast<const uint32_t*>(p + 16);
                a[mb][3] = *reinterpret_cast<const uint32_t*>(p + 8*SPB + 16);
            }
#pragma unroll
            for (int nb = 0; nb < 4; ++nb) {
                const char* p = Bhi + boff + nb*8*SPB + co;
                bh[nb][0] = *reinterpret_cast<const uint32_t*>(p);
                bh[nb][1] = *reinterpret_cast<const uint32_t*>(p + 16);
            }
            // hi * hi
#pragma unroll
            for (int mb = 0; mb < 2; ++mb)
#pragma unroll
                for (int nb = 0; nb < 4; ++nb)
                    MMA16816(acc[mb][nb], a[mb], bh[nb]);
            // hi * lo
#pragma unroll
            for (int nb = 0; nb < 4; ++nb) {
                const char* p = Blo + boff + nb*8*SPB + co;
                bl[nb][0] = *reinterpret_cast<const uint32_t*>(p);
                bl[nb][1] = *reinterpret_cast<const uint32_t*>(p + 16);
            }
#pragma unroll
            for (int mb = 0; mb < 2; ++mb)
#pragma unroll
                for (int nb = 0; nb < 4; ++nb)
                    MMA16816(acc[mb][nb], a[mb], bl[nb]);
            // lo * hi (reuse a[] for Q-lo)
#pragma unroll
            for (int mb = 0; mb < 2; ++mb) {
                const char* p = sQlo + aoff + mb*16*SPB + co;
                a[mb][0] = *reinterpret_cast<const uint32_t*>(p);
                a[mb][1] = *reinterpret_cast<const uint32_t*>(p + 8*SPB);
                a[mb][2] = *reinterpret_cast<const uint32_t*>(p + 16);
                a[mb][3] = *reinterpret_cast<const uint32_t*>(p + 8*SPB + 16);
            }
#pragma unroll
            for (int mb = 0; mb < 2; ++mb)
#pragma unroll
                for (int nb = 0; nb < 4; ++nb)
                    MMA16816(acc[mb][nb], a[mb], bh[nb]);
        }

        __syncthreads();                    // all warps done reading sK[buf]
        if (kt + 2 < NKT) issue_stage(kt + 2);

        // ---- fold 32x32 logits into per-lane running softmax (FMA pipe) ----
#pragma unroll
        for (int nb = 0; nb < 4; ++nb) {
            const int col = kt*TK + wn*32 + nb*8 + tig*2;   // even; cx+1 never wraps
            const int cyi = col / WW;
            const float cy = (float)cyi;
            const float cx0 = (float)(col - cyi*WW);
#pragma unroll
            for (int mb = 0; mb < 2; ++mb) {
#pragma unroll
                for (int r = 0; r < 4; ++r) {
                    const int slot = mb*2 + (r >> 1);       // r0,r1 -> row g; r2,r3 -> g+8
                    const float cx = (r & 1) ? (cx0 + 1.f) : cx0;
                    float d = acc[mb][nb][r];
                    d = fminf(fmaxf(d, -1.02f), 1.02f);
                    float e = exp_scaled(d);
                    pS[slot] += e;
                    pX[slot] += e * cx;
                    pY[slot] += e * cy;
                    pM[slot]  = fmaxf(pM[slot], d);
                }
            }
        }
    }

    // ---- reduce across tig lanes (same row, different cols) ----
#pragma unroll
    for (int s = 0; s < 4; ++s) {
#pragma unroll
        for (int d = 1; d <= 2; d <<= 1) {
            pS[s] += __shfl_xor_sync(0xffffffff, pS[s], d);
            pX[s] += __shfl_xor_sync(0xffffffff, pX[s], d);
            pY[s] += __shfl_xor_sync(0xffffffff, pY[s], d);
            pM[s]  = fmaxf(pM[s], __shfl_xor_sync(0xffffffff, pM[s], d));
        }
    }

    // ---- cross-warp (wn) reduction via smem; reuse sQhi region ----
    float* red = reinterpret_cast<float*>(dsm);   // [4 stats][128 rows][4 wn]
    if (tig == 0) {
#pragma unroll
        for (int s = 0; s < 4; ++s) {
            int row = wm*32 + (s >> 1)*16 + g + (s & 1)*8;
            red[(0*128 + row)*4 + wn] = pS[s];
            red[(1*128 + row)*4 + wn] = pX[s];
            red[(2*128 + row)*4 + wn] = pY[s];
            red[(3*128 + row)*4 + wn] = pM[s];
        }
    }
    __syncthreads();

    if (tid < 128) {
        const int row = tid;
        float s = 0.f, xs = 0.f, ys = 0.f, m = -4.f;
#pragma unroll
        for (int t = 0; t < 4; ++t) {
            s  += red[(0*128 + row)*4 + t];
            xs += red[(1*128 + row)*4 + t];
            ys += red[(2*128 + row)*4 + t];
            m   = fmaxf(m, red[(3*128 + row)*4 + t]);
        }
        const int p = qbase + row;
        const float xsrc = (float)(p % WW);
        const float ysrc = (float)(p / WW);
        const float invs = 1.0f / s;
        out[((size_t)b*2 + 0)*HWD + p] = xs * invs - xsrc;
        out[((size_t)b*2 + 1)*HWD + p] = ys * invs - ysrc;
        out[(size_t)BB*2*HWD + (size_t)b*HWD + p] = exp_scaled(m) * invs;
    }
}

// ---------------------------------------------------------------------------
extern "C" void kernel_launch(void* const* d_in, const int* in_sizes, int n_in,
                              void* d_out, int out_size) {
    const float* fL = (const float*)d_in[0];
    const float* fR = (const float*)d_in[1];
    float* out = (float*)d_out;

    {
        dim3 grid(HWD/128, BB, 2);
        decomp_kernel<<<grid, 256>>>(fL, fR);
    }
    {
        const int smem_bytes = 2*TILEB + 2*STAGEB + 32;   // 208928
        cudaFuncSetAttribute(corr_kernel,
                             cudaFuncAttributeMaxDynamicSharedMemorySize, smem_bytes);
        dim3 grid(HWD / TQ, BB);
        corr_kernel<<<grid, NTHREADS, smem_bytes>>>(out);
    }
}

// round 14
// speedup vs baseline: 1.5075x; 1.4308x over previous
#include <cuda_runtime.h>
#include <cuda_bf16.h>
#include <cstdint>
#include <math.h>

#define BB 2
#define CC 128
#define WW 96
#define HWD 9216
#define TQ 128
#define TK2 64                // columns per group tile
#define NT2 (HWD/TK2)         // 144 tiles; group A even, group B odd
#define NTHREADS 512
#define SP 136                // padded smem row stride in bf16
#define SPB (SP*2)            // 272 bytes
#define TILEB (128*SPB)       // 34816 B: one stage (64 rows hi + 64 rows lo) or Q tile
#define QB (2*TILEB)          // Q hi + Q lo

// Decomposed, normalized features: [B][HW][C] bf16, row-major.
__device__ __nv_bfloat16 g_qhi[BB*HWD*CC];
__device__ __nv_bfloat16 g_qlo[BB*HWD*CC];
__device__ __nv_bfloat16 g_khi[BB*HWD*CC];
__device__ __nv_bfloat16 g_klo[BB*HWD*CC];

// ---------------------------------------------------------------------------
// exp(s*a), a in [-1.02,1.02], s = 1/(sqrt(128)*0.1). Degree-7 Taylor with the
// scale folded in; pure FMA pipe. |rel err| < 1e-5 on the domain (tolerance
// 1e-3). Valid since unit vectors => |dot|<=1, the ref's +-50 clamp never binds.
// ---------------------------------------------------------------------------
__device__ __forceinline__ float exp_scaled(float a) {
    const float c7 = 8.362471e-5f;
    const float c6 = 6.622738e-4f;
    const float c5 = 4.495664e-3f;
    const float c4 = 2.543132e-2f;
    const float c3 = 1.150890e-1f;
    const float c2 = 3.90625e-1f;       // s^2/2 (s^2 = 0.78125 exact)
    const float c1 = 0.8838834764831844f;
    float p = c7;
    p = fmaf(p, a, c6); p = fmaf(p, a, c5); p = fmaf(p, a, c4);
    p = fmaf(p, a, c3); p = fmaf(p, a, c2); p = fmaf(p, a, c1);
    p = fmaf(p, a, 1.0f);
    return p;
}

// ---------------------------------------------------------------------------
// PTX helpers (baseline PTX only: mbarrier, cp.async.bulk, mma.sync, bar.sync)
// ---------------------------------------------------------------------------
__device__ __forceinline__ uint32_t smem_u32(const void* p) {
    uint32_t a;
    asm("{ .reg .u64 t; cvta.to.shared.u64 t, %1; cvt.u32.u64 %0, t; }" : "=r"(a) : "l"(p));
    return a;
}
__device__ __forceinline__ void mbar_init(uint32_t a, uint32_t n) {
    asm volatile("mbarrier.init.shared.b64 [%0], %1;" :: "r"(a), "r"(n) : "memory");
}
__device__ __forceinline__ void mbar_expect_tx(uint32_t a, uint32_t bytes) {
    asm volatile("mbarrier.arrive.expect_tx.shared.b64 _, [%0], %1;"
                 :: "r"(a), "r"(bytes) : "memory");
}
__device__ __forceinline__ void mbar_wait(uint32_t addr, uint32_t parity) {
    uint32_t done;
    asm volatile(
        "{\n\t.reg .pred p;\n\t"
        "mbarrier.try_wait.parity.acquire.cta.shared::cta.b64 p, [%1], %2;\n\t"
        "selp.b32 %0, 1, 0, p;\n\t}"
        : "=r"(done) : "r"(addr), "r"(parity) : "memory");
    if (!done) {
        asm volatile(
            "{\n\t.reg .pred P1;\n\t"
            "WAIT_LOOP_%=:\n\t"
            "mbarrier.try_wait.parity.acquire.cta.shared::cta.b64 P1, [%0], %1, 0x989680;\n\t"
            "@P1 bra.uni WAIT_DONE_%=;\n\t"
            "bra.uni WAIT_LOOP_%=;\n\t"
            "WAIT_DONE_%=:\n\t}"
            :: "r"(addr), "r"(parity) : "memory");
    }
}
__device__ __forceinline__ void bulk_copy(uint32_t dst, const void* src, uint32_t mbar) {
    asm volatile(
        "cp.async.bulk.shared::cta.global.mbarrier::complete_tx::bytes [%0], [%1], %2, [%3];"
        :: "r"(dst), "l"(src), "n"(256), "r"(mbar) : "memory");
}
__device__ __forceinline__ void group_bar(uint32_t id) {
    asm volatile("bar.sync %0, %1;" :: "r"(id), "n"(256) : "memory");
}

// mma.sync m16n8k16 row.col bf16 -> fp32
#define MMA16816(d, a, b) \
    asm volatile("mma.sync.aligned.m16n8k16.row.col.f32.bf16.bf16.f32 " \
        "{%0,%1,%2,%3}, {%4,%5,%6,%7}, {%8,%9}, {%0,%1,%2,%3};" \
        : "+f"((d)[0]), "+f"((d)[1]), "+f"((d)[2]), "+f"((d)[3]) \
        : "r"((a)[0]), "r"((a)[1]), "r"((a)[2]), "r"((a)[3]), \
          "r"((b)[0]), "r"((b)[1]))

// ---------------------------------------------------------------------------
// Kernel 1: normalize + transpose + split-bf16 decompose.
// ---------------------------------------------------------------------------
__global__ void __launch_bounds__(256)
decomp_kernel(const float* __restrict__ fL, const float* __restrict__ fR) {
    __shared__ float s[CC*129];
    __shared__ float s_part[256];
    __shared__ float s_inv[128];

    const int pbase = blockIdx.x * 128;
    const int b     = blockIdx.y;
    const float* src = (blockIdx.z ? fR : fL) + (size_t)b * CC * HWD;
    __nv_bfloat16* dhi = blockIdx.z ? g_khi : g_qhi;
    __nv_bfloat16* dlo = blockIdx.z ? g_klo : g_qlo;
    const int tid = threadIdx.x;

    for (int idx = tid; idx < CC*32; idx += 256) {
        int c  = idx >> 5;
        int p4 = (idx & 31) << 2;
        float4 v = *reinterpret_cast<const float4*>(src + (size_t)c*HWD + pbase + p4);
        float* d = s + c*129 + p4;
        d[0]=v.x; d[1]=v.y; d[2]=v.z; d[3]=v.w;
    }
    __syncthreads();
    {
        int pos = tid & 127, half = tid >> 7;
        float ss = 0.f;
#pragma unroll 8
        for (int c = half*64; c < half*64 + 64; ++c) { float v = s[c*129 + pos]; ss += v*v; }
        s_part[tid] = ss;
    }
    __syncthreads();
    if (tid < 128)
        s_inv[tid] = 1.0f / fmaxf(sqrtf(s_part[tid] + s_part[tid+128]), 1e-6f);
    __syncthreads();

    for (int idx = tid; idx < 128*64; idx += 256) {
        int c2 = idx & 63, pos = idx >> 6;
        float inv = s_inv[pos];
        float f0 = s[(2*c2  )*129 + pos] * inv;
        float f1 = s[(2*c2+1)*129 + pos] * inv;
        __nv_bfloat162 h = __floats2bfloat162_rn(f0, f1);
        float l0 = f0 - __bfloat162float(h.x);
        float l1 = f1 - __bfloat162float(h.y);
        __nv_bfloat162 l = __floats2bfloat162_rn(l0, l1);
        size_t o = ((size_t)b*HWD + pbase + pos) * CC + 2*c2;
        *reinterpret_cast<uint32_t*>(&dhi[o]) = *reinterpret_cast<const uint32_t*>(&h);
        *reinterpret_cast<uint32_t*>(&dlo[o]) = *reinterpret_cast<const uint32_t*>(&l);
    }
}

// ---------------------------------------------------------------------------
// Kernel 2: dual-group mma.sync correlation + one-pass softmax.
// 16 warps: group A (0-7) even 64-col k-tiles, group B (8-15) odd tiles.
// Per group: warps 2(wm: 64 rows) x 4(wn: 16 cols), warp tile 64x16 per tile.
// Each group: own double-buffered stages + own named barrier -> MMA of one
// group overlaps fold of the other (no CTA-wide sync in the loop).
// smem: Qhi | Qlo | stage0..3 (A:0,1  B:2,3) | mbarriers
// ---------------------------------------------------------------------------
extern __shared__ char dsm[];

__global__ void __launch_bounds__(NTHREADS, 1)
corr_kernel(float* __restrict__ out) {
    const int tid  = threadIdx.x;
    const int wid  = tid >> 5;
    const int lane = tid & 31;
    const int g    = lane >> 2;
    const int tig  = lane & 3;
    const int grp  = wid >> 3;        // 0 = A, 1 = B
    const int wg   = wid & 7;         // warp within group
    const int wm   = wg >> 2;         // 0..1 (64 rows each)
    const int wn   = wg & 3;          // 0..3 (16 cols each)
    const int b     = blockIdx.y;
    const int qbase = blockIdx.x * TQ;

    char* sQhi = dsm;
    char* sQlo = dsm + TILEB;
    char* sStg = dsm + QB;                 // 4 stages of TILEB
    const uint32_t mbar0 = smem_u32(dsm) + (uint32_t)(QB + 4*TILEB);
    const uint32_t stg0  = smem_u32(sStg);

    const __nv_bfloat16* qhi  = g_qhi + ((size_t)b*HWD + qbase) * CC;
    const __nv_bfloat16* qlo  = g_qlo + ((size_t)b*HWD + qbase) * CC;
    const __nv_bfloat16* khiB = g_khi + (size_t)b*HWD*CC;
    const __nv_bfloat16* kloB = g_klo + (size_t)b*HWD*CC;

    if (tid == 0)
        for (int j = 0; j < 4; ++j) mbar_init(mbar0 + j*8, 1);

    // ---- load Q tiles (both groups share Q) ----
    for (int idx = tid; idx < 128*16; idx += NTHREADS) {
        int row = idx >> 4, c4 = idx & 15;
        *reinterpret_cast<float4*>(sQhi + row*SPB + c4*16) =
            reinterpret_cast<const float4*>(qhi + (size_t)row*CC)[c4];
        *reinterpret_cast<float4*>(sQlo + row*SPB + c4*16) =
            reinterpret_cast<const float4*>(qlo + (size_t)row*CC)[c4];
    }
    __syncthreads();   // mbarriers + Q visible to all

    // ---- per-group stage loader (loader warp = first warp of group) ----
    const bool is_loader = (wg == 0);
    auto issue_load = [&](int i, int j) {   // tile i -> stage j (warp-collective)
        const uint32_t mb = mbar0 + j*8;
        if (lane == 0) mbar_expect_tx(mb, 64*256*2);
        __syncwarp();
        const uint32_t dst = stg0 + j*TILEB;
#pragma unroll
        for (int r = lane; r < 64; r += 32) {
            bulk_copy(dst + r*SPB,            khiB + (size_t)(i*TK2 + r)*CC, mb);
            bulk_copy(dst + 64*SPB + r*SPB,   kloB + (size_t)(i*TK2 + r)*CC, mb);
        }
    };

    if (is_loader) {
        issue_load(grp,     2*grp);
        issue_load(grp + 2, 2*grp + 1);
    }

    uint32_t ph[2] = {0, 0};

    // per-lane softmax accumulators: 8 row slots (4 mb x 2 half-rows)
    float pS[8], pX[8], pY[8], pM[8];
#pragma unroll
    for (int i = 0; i < 8; ++i) { pS[i]=0.f; pX[i]=0.f; pY[i]=0.f; pM[i]=-4.f; }

    const int aoff = (wm*64 + g)*SPB + tig*4;       // A-frag base (within Q)
    const int boff = (wn*16 + g)*SPB + tig*4;       // B-frag base (within stage)

    for (int t = 0; t < NT2/2; ++t) {
        const int i  = grp + 2*t;         // this group's tile index
        const int bs = t & 1;
        const int j  = 2*grp + bs;        // stage slot
        mbar_wait(mbar0 + j*8, ph[bs]); ph[bs] ^= 1;

        const char* Shi = sStg + j*TILEB;
        const char* Slo = Shi + 64*SPB;

        float acc[4][2][4];
#pragma unroll
        for (int mb = 0; mb < 4; ++mb)
#pragma unroll
            for (int nb = 0; nb < 2; ++nb)
#pragma unroll
                for (int r = 0; r < 4; ++r) acc[mb][nb][r] = 0.f;

#pragma unroll
        for (int ks = 0; ks < 8; ++ks) {
            const int co = ks*32;   // 16 chans * 2B
            uint32_t bh0[2], bh1[2], bl0[2], bl1[2];
            {
                const char* p0 = Shi + boff + co;
                bh0[0] = *reinterpret_cast<const uint32_t*>(p0);
                bh0[1] = *reinterpret_cast<const uint32_t*>(p0 + 16);
                bh1[0] = *reinterpret_cast<const uint32_t*>(p0 + 8*SPB);
                bh1[1] = *reinterpret_cast<const uint32_t*>(p0 + 8*SPB + 16);
                const char* p1 = Slo + boff + co;
                bl0[0] = *reinterpret_cast<const uint32_t*>(p1);
                bl0[1] = *reinterpret_cast<const uint32_t*>(p1 + 16);
                bl1[0] = *reinterpret_cast<const uint32_t*>(p1 + 8*SPB);
                bl1[1] = *reinterpret_cast<const uint32_t*>(p1 + 8*SPB + 16);
            }
#pragma unroll
            for (int mb = 0; mb < 4; ++mb) {
                uint32_t a[4];
                const char* pa = sQhi + aoff + mb*16*SPB + co;
                a[0] = *reinterpret_cast<const uint32_t*>(pa);
                a[1] = *reinterpret_cast<const uint32_t*>(pa + 8*SPB);
                a[2] = *reinterpret_cast<const uint32_t*>(pa + 16);
                a[3] = *reinterpret_cast<const uint32_t*>(pa + 8*SPB + 16);
                MMA16816(acc[mb][0], a, bh0);
                MMA16816(acc[mb][1], a, bh1);
                MMA16816(acc[mb][0], a, bl0);
                MMA16816(acc[mb][1], a, bl1);
                const char* pl = sQlo + aoff + mb*16*SPB + co;
                a[0] = *reinterpret_cast<const uint32_t*>(pl);
                a[1] = *reinterpret_cast<const uint32_t*>(pl + 8*SPB);
                a[2] = *reinterpret_cast<const uint32_t*>(pl + 16);
                a[3] = *reinterpret_cast<const uint32_t*>(pl + 8*SPB + 16);
                MMA16816(acc[mb][0], a, bh0);
                MMA16816(acc[mb][1], a, bh1);
            }
        }

        group_bar(1 + grp);               // all group warps done reading stage j
        if (is_loader && i + 4 < NT2) issue_load(i + 4, j);

        // ---- fold 64x16 warp-tile logits (overlaps other group's MMA) ----
#pragma unroll
        for (int nb = 0; nb < 2; ++nb) {
            const int col = i*TK2 + wn*16 + nb*8 + tig*2;   // even, +1 never wraps
            const int cyi = col / WW;
            const float cy  = (float)cyi;
            const float cx0 = (float)(col - cyi*WW);
#pragma unroll
            for (int mb = 0; mb < 4; ++mb) {
#pragma unroll
                for (int r = 0; r < 4; ++r) {
                    const int slot = mb*2 + (r >> 1);
                    const float cx = (r & 1) ? (cx0 + 1.f) : cx0;
                    float d = acc[mb][nb][r];
                    d = fminf(fmaxf(d, -1.02f), 1.02f);
                    float e = exp_scaled(d);
                    pS[slot] += e;
                    pX[slot] += e * cx;
                    pY[slot] += e * cy;
                    pM[slot]  = fmaxf(pM[slot], d);
                }
            }
        }
    }

    // ---- reduce across tig lanes (same row, different cols) ----
#pragma unroll
    for (int s = 0; s < 8; ++s) {
#pragma unroll
        for (int d = 1; d <= 2; d <<= 1) {
            pS[s] += __shfl_xor_sync(0xffffffff, pS[s], d);
            pX[s] += __shfl_xor_sync(0xffffffff, pX[s], d);
            pY[s] += __shfl_xor_sync(0xffffffff, pY[s], d);
            pM[s]  = fmaxf(pM[s], __shfl_xor_sync(0xffffffff, pM[s], d));
        }
    }

    // ---- cross-warp & cross-group reduction via smem (reuse Q region) ----
    __syncthreads();                       // both groups fully done with Q/stages
    float* red = reinterpret_cast<float*>(dsm);   // [4 stats][128 rows][8]
    if (tig == 0) {
        const int pidx = grp*4 + wn;
#pragma unroll
        for (int s = 0; s < 8; ++s) {
            int row = wm*64 + (s >> 1)*16 + (s & 1)*8 + g;
            red[(0*128 + row)*8 + pidx] = pS[s];
            red[(1*128 + row)*8 + pidx] = pX[s];
            red[(2*128 + row)*8 + pidx] = pY[s];
            red[(3*128 + row)*8 + pidx] = pM[s];
        }
    }
    __syncthreads();

    if (tid < 128) {
        const int row = tid;
        float s = 0.f, xs = 0.f, ys = 0.f, m = -4.f;
#pragma unroll
        for (int t = 0; t < 8; ++t) {
            s  += red[(0*128 + row)*8 + t];
            xs += red[(1*128 + row)*8 + t];
            ys += red[(2*128 + row)*8 + t];
            m   = fmaxf(m, red[(3*128 + row)*8 + t]);
        }
        const int p = qbase + row;
        const float xsrc = (float)(p % WW);
        const float ysrc = (float)(p / WW);
        const float invs = 1.0f / s;
        out[((size_t)b*2 + 0)*HWD + p] = xs * invs - xsrc;
        out[((size_t)b*2 + 1)*HWD + p] = ys * invs - ysrc;
        out[(size_t)BB*2*HWD + (size_t)b*HWD + p] = exp_scaled(m) * invs;
    }
}

// ---------------------------------------------------------------------------
extern "C" void kernel_launch(void* const* d_in, const int* in_sizes, int n_in,
                              void* d_out, int out_size) {
    const float* fL = (const float*)d_in[0];
    const float* fR = (const float*)d_in[1];
    float* out = (float*)d_out;

    {
        dim3 grid(HWD/128, BB, 2);
        decomp_kernel<<<grid, 256>>>(fL, fR);
    }
    {
        const int smem_bytes = QB + 4*TILEB + 32;   // 208928
        cudaFuncSetAttribute(corr_kernel,
                             cudaFuncAttributeMaxDynamicSharedMemorySize, smem_bytes);
        dim3 grid(HWD / TQ, BB);
        corr_kernel<<<grid, NTHREADS, smem_bytes>>>(out);
    }
}